// round 9
// baseline (speedup 1.0000x reference)
#include <cuda_runtime.h>
#include <cuda_bf16.h>

// out[b,d,n] = w[d] * in[b,d,n];  B=8, D=2048, N=2048, fp32.
// R8: resubmit of R7 (infra failure, kernel is hang-proof): proven MLP-4
// LDG.128 stream, 2048 CTAs x 16 f4/thread, per-CTA contiguous 64KB chunk,
// exact cover, no guards.

static constexpr int B = 8;
static constexpr int D = 2048;
static constexpr int N = 2048;
static constexpr long long TOTAL4 = (long long)B * D * N / 4;  // 8,388,608 float4
static constexpr int THREADS = 256;
static constexpr int UNROLL  = 4;                              // f4 per inner batch
static constexpr int OUTER   = 4;                              // batches per thread
static constexpr int CTA_F4  = THREADS * UNROLL * OUTER;       // 4096 f4 = 64KB
static constexpr long long NUM_CTAS = TOTAL4 / CTA_F4;         // 2048, exact

__global__ void __launch_bounds__(THREADS)
channel_scale_kernel(const float4* __restrict__ in,
                     const float*  __restrict__ w,
                     float4*       __restrict__ out)
{
    long long cta_base = (long long)blockIdx.x * CTA_F4;

#pragma unroll
    for (int it = 0; it < OUTER; it++) {
        long long base = cta_base + it * (THREADS * UNROLL) + threadIdx.x;

        // Front-batch 4 independent LDG.128 (proven best MLP shape).
        float4 v[UNROLL];
#pragma unroll
        for (int k = 0; k < UNROLL; k++) {
            v[k] = in[base + (long long)k * THREADS];
        }

#pragma unroll
        for (int k = 0; k < UNROLL; k++) {
            long long i = base + (long long)k * THREADS;
            // channel index: (i4 / (N/4)) % D ; N/4 = 512, D = 2048
            int d = (int)((i >> 9) & (D - 1));
            float s = __ldg(w + d);          // 8 KB, L2-resident
            v[k].x *= s; v[k].y *= s; v[k].z *= s; v[k].w *= s;
            out[i] = v[k];
        }
    }
}

extern "C" void kernel_launch(void* const* d_in, const int* in_sizes, int n_in,
                              void* d_out, int out_size)
{
    const float4* in = (const float4*)d_in[0];   // inputs [B, D, N] fp32
    const float*  w  = (const float*)d_in[1];    // attention_weights [D] fp32
    float4* out = (float4*)d_out;

    channel_scale_kernel<<<(unsigned)NUM_CTAS, THREADS>>>(in, w, out);
}

// round 12
// speedup vs baseline: 1.0078x; 1.0078x over previous
#include <cuda_runtime.h>
#include <cuda_bf16.h>

// out[b,d,n] = w[d] * in[b,d,n];  B=8, D=2048, N=2048, fp32.
// FINAL (resubmit; R10 was an infra failure on this exact source, which
// already passed at 43.5us wall in Round 2): HBM-bound stream at the measured
// R/W-mix DRAM ceiling (~5.9-6.0 TB/s, 75% of spec). Seven structural
// variants (MLP 1/4/8, .cs hints, 256-bit ld/st, TMA bulk store, 1/2/7-wave
// tilings) all land 71-76% DRAM; this config holds the best kernel (35.6us)
// and wall (43.5us). Front-batched 4x independent LDG.128 per thread, plain
// STG.128, exact-cover grid, weights (8KB) L2-resident via __ldg.

static constexpr int B = 8;
static constexpr int D = 2048;
static constexpr int N = 2048;
static constexpr long long TOTAL4 = (long long)B * D * N / 4;  // 8,388,608 float4
static constexpr int THREADS = 256;
static constexpr int UNROLL  = 4;
static constexpr int BLOCK_ELEMS = THREADS * UNROLL;           // 1024 float4 / block

__global__ void __launch_bounds__(THREADS)
channel_scale_kernel(const float4* __restrict__ in,
                     const float*  __restrict__ w,
                     float4*       __restrict__ out)
{
    long long base = (long long)blockIdx.x * BLOCK_ELEMS + threadIdx.x;

    // Front-batch all loads: 4 independent LDG.128 in flight per thread.
    float4 v[UNROLL];
#pragma unroll
    for (int k = 0; k < UNROLL; k++) {
        v[k] = in[base + (long long)k * THREADS];
    }

#pragma unroll
    for (int k = 0; k < UNROLL; k++) {
        long long i = base + (long long)k * THREADS;
        // channel index: i4 / (N/4) % D ; N/4 = 512, D = 2048
        int d = (int)((i >> 9) & (D - 1));
        float s = __ldg(w + d);          // L1/L2 resident (8 KB)
        v[k].x *= s; v[k].y *= s; v[k].z *= s; v[k].w *= s;
        out[i] = v[k];
    }
}

extern "C" void kernel_launch(void* const* d_in, const int* in_sizes, int n_in,
                              void* d_out, int out_size)
{
    const float4* in = (const float4*)d_in[0];   // inputs [B, D, N] fp32
    const float*  w  = (const float*)d_in[1];    // attention_weights [D] fp32
    float4* out = (float4*)d_out;

    long long blocks = TOTAL4 / BLOCK_ELEMS;     // 8192, exact cover
    channel_scale_kernel<<<(unsigned)blocks, THREADS>>>(in, w, out);
}